// round 12
// baseline (speedup 1.0000x reference)
#include <cuda_runtime.h>

#define THREADS 256
#define NUM_TOKENS (128 * 8192)
#define TOK_PER_BLOCK (THREADS * 2)   // 512, divides NUM_TOKENS exactly
#define ZF_STRIDE 257                 // odd stride, conflict-free u64 rows

typedef unsigned long long u64;

__device__ __forceinline__ u64 pack2(float lo, float hi) {
    u64 r; asm("mov.b64 %0, {%1, %2};" : "=l"(r) : "f"(lo), "f"(hi)); return r;
}
__device__ __forceinline__ u64 dup2(float v) { return pack2(v, v); }
__device__ __forceinline__ void unpack2(u64 p, float& lo, float& hi) {
    asm("mov.b64 {%0, %1}, %2;" : "=f"(lo), "=f"(hi) : "l"(p));
}
__device__ __forceinline__ u64 fma2(u64 a, u64 b, u64 c) {
    u64 d; asm("fma.rn.f32x2 %0, %1, %2, %3;" : "=l"(d) : "l"(a), "l"(b), "l"(c)); return d;
}
__device__ __forceinline__ u64 add2(u64 a, u64 b) {
    u64 d; asm("add.rn.f32x2 %0, %1, %2;" : "=l"(d) : "l"(a), "l"(b)); return d;
}
__device__ __forceinline__ u64 mul2(u64 a, u64 b) {
    u64 d; asm("mul.rn.f32x2 %0, %1, %2;" : "=l"(d) : "l"(a), "l"(b)); return d;
}

__global__ __launch_bounds__(THREADS, 3) void qtb_kernel(
    const float* __restrict__ x,
    const float* __restrict__ Wq,  const float* __restrict__ bq,
    const float* __restrict__ theta_attn,
    const float* __restrict__ Wc,  const float* __restrict__ bc,
    const float* __restrict__ g1,  const float* __restrict__ beta1,
    const float* __restrict__ theta_ffn,
    const float* __restrict__ W1,  const float* __restrict__ b1,
    const float* __restrict__ W2,  const float* __restrict__ b2,
    const float* __restrict__ g2,  const float* __restrict__ beta2,
    float* __restrict__ out)
{
    __shared__ __align__(16) float sWq[64], sWc[64], sW1[256], sW2[256];
    __shared__ __align__(16) u64 sbqth[4], sbcp[4], sb1p[16], sb2p[4];
    __shared__ __align__(16) u64 sg1p[4], sbe1p[4], sg2p[4], sbe2p[4];
    __shared__ float sctf[8];
    // zf parked here pre-duplicated; each thread touches only col==tid (no sync needed)
    __shared__ __align__(16) u64 szf[16 * ZF_STRIDE];

    const int tid = threadIdx.x;
    if (tid < 64) { sWq[tid] = Wq[tid]; sWc[tid] = Wc[tid]; }
    sW1[tid] = W1[tid];
    sW2[tid] = W2[tid];
    if (tid < 4) {
        sbqth[tid] = pack2(bq[2*tid] + theta_attn[2*tid], bq[2*tid+1] + theta_attn[2*tid+1]);
        sbcp[tid]  = pack2(bc[2*tid],  bc[2*tid+1]);
        sb2p[tid]  = pack2(b2[2*tid],  b2[2*tid+1]);
        sg1p[tid]  = pack2(g1[2*tid],  g1[2*tid+1]);
        sbe1p[tid] = pack2(beta1[2*tid], beta1[2*tid+1]);
        sg2p[tid]  = pack2(g2[2*tid],  g2[2*tid+1]);
        sbe2p[tid] = pack2(beta2[2*tid], beta2[2*tid+1]);
    }
    if (tid < 16) sb1p[tid] = pack2(b1[2*tid], b1[2*tid+1]);
    if (tid < 8)  sctf[tid] = __cosf(theta_ffn[tid]);
    __syncthreads();

    const int t0 = blockIdx.x * TOK_PER_BLOCK + tid;   // token A
    const int t1 = t0 + THREADS;                       // token B (coalesced)

    // ---- load both tokens
    float xs[2][8];
    {
        const float4* xin = reinterpret_cast<const float4*>(x);
        float4 A0 = xin[(size_t)t0 * 2], A1 = xin[(size_t)t0 * 2 + 1];
        float4 B0 = xin[(size_t)t1 * 2], B1 = xin[(size_t)t1 * 2 + 1];
        xs[0][0]=A0.x; xs[0][1]=A0.y; xs[0][2]=A0.z; xs[0][3]=A0.w;
        xs[0][4]=A1.x; xs[0][5]=A1.y; xs[0][6]=A1.z; xs[0][7]=A1.w;
        xs[1][0]=B0.x; xs[1][1]=B0.y; xs[1][2]=B0.z; xs[1][3]=B0.w;
        xs[1][4]=B1.x; xs[1][5]=B1.y; xs[1][6]=B1.z; xs[1][7]=B1.w;
    }

    // ---- q = x @ Wq + (bq + theta): output-packed, dups hoisted, weights shared by 2 tokens
    u64 q[2][4];
#pragma unroll
    for (int p = 0; p < 4; p++) { q[0][p] = sbqth[p]; q[1][p] = sbqth[p]; }
    {
        const ulonglong2* wq2 = reinterpret_cast<const ulonglong2*>(sWq);
#pragma unroll
        for (int j = 0; j < 8; j++) {
            ulonglong2 wa = wq2[j*2], wb = wq2[j*2+1];
            u64 d0 = dup2(xs[0][j]), d1 = dup2(xs[1][j]);
            q[0][0] = fma2(d0, wa.x, q[0][0]); q[0][1] = fma2(d0, wa.y, q[0][1]);
            q[0][2] = fma2(d0, wb.x, q[0][2]); q[0][3] = fma2(d0, wb.y, q[0][3]);
            q[1][0] = fma2(d1, wa.x, q[1][0]); q[1][1] = fma2(d1, wa.y, q[1][1]);
            q[1][2] = fma2(d1, wb.x, q[1][2]); q[1][3] = fma2(d1, wb.y, q[1][3]);
        }
    }

    // ---- ca = cos(q); z = cumulative products
    float z[2][8];
#pragma unroll
    for (int T = 0; T < 2; T++) {
        float ca[8];
#pragma unroll
        for (int p = 0; p < 4; p++) {
            float lo, hi; unpack2(q[T][p], lo, hi);
            ca[2*p] = __cosf(lo); ca[2*p+1] = __cosf(hi);
        }
        float pref = ca[0];
#pragma unroll
        for (int k = 1; k < 8; k++) { pref *= ca[k]; z[T][k] = pref; }
        float r = ca[1];
#pragma unroll
        for (int k = 2; k < 8; k++) r *= ca[k];
        z[T][0] = r;
    }

    // ---- attn = z @ Wc + bc (reuse q accumulators)
#pragma unroll
    for (int p = 0; p < 4; p++) { q[0][p] = sbcp[p]; q[1][p] = sbcp[p]; }
    {
        const ulonglong2* wc2 = reinterpret_cast<const ulonglong2*>(sWc);
#pragma unroll
        for (int j = 0; j < 8; j++) {
            ulonglong2 wa = wc2[j*2], wb = wc2[j*2+1];
            u64 d0 = dup2(z[0][j]), d1 = dup2(z[1][j]);
            q[0][0] = fma2(d0, wa.x, q[0][0]); q[0][1] = fma2(d0, wa.y, q[0][1]);
            q[0][2] = fma2(d0, wb.x, q[0][2]); q[0][3] = fma2(d0, wb.y, q[0][3]);
            q[1][0] = fma2(d1, wa.x, q[1][0]); q[1][1] = fma2(d1, wa.y, q[1][1]);
            q[1][2] = fma2(d1, wb.x, q[1][2]); q[1][3] = fma2(d1, wb.y, q[1][3]);
        }
    }

    // ---- LN1 packed (R8 form); x1 kept as scalars; zf DUP'D and parked in smem
    float x1[2][8];
#pragma unroll
    for (int T = 0; T < 2; T++) {
        u64 vp[4];
#pragma unroll
        for (int p = 0; p < 4; p++)
            vp[p] = add2(q[T][p], pack2(xs[T][2*p], xs[T][2*p+1]));
        u64 tA = add2(vp[0], vp[1]);
        u64 tB = add2(vp[2], vp[3]);
        u64 tC = add2(tA, tB);
        float slo, shi; unpack2(tC, slo, shi);
        float m = (slo + shi) * 0.125f;
        u64 negm = dup2(-m);
        u64 dp[4];
#pragma unroll
        for (int p = 0; p < 4; p++) dp[p] = add2(vp[p], negm);
        u64 vr = mul2(dp[0], dp[0]);
        vr = fma2(dp[1], dp[1], vr);
        vr = fma2(dp[2], dp[2], vr);
        vr = fma2(dp[3], dp[3], vr);
        float vlo, vhi; unpack2(vr, vlo, vhi);
        float rs = rsqrtf((vlo + vhi) * 0.125f + 1e-5f);
        u64 rsd = dup2(rs);
#pragma unroll
        for (int p = 0; p < 4; p++) {
            u64 x1p = fma2(mul2(dp[p], rsd), sg1p[p], sbe1p[p]);
            float lo, hi; unpack2(x1p, lo, hi);
            x1[T][2*p]   = lo;
            x1[T][2*p+1] = hi;
            szf[(T*8 + 2*p)     * ZF_STRIDE + tid] = dup2(sctf[2*p]   * __cosf(lo));
            szf[(T*8 + 2*p + 1) * ZF_STRIDE + tid] = dup2(sctf[2*p+1] * __cosf(hi));
        }
    }

    // ---- FFN, two k-halves (R6-proven): h[2][8] packed chains; zf-dups read from smem.
    u64 ff[2][4];
#pragma unroll
    for (int p = 0; p < 4; p++) { ff[0][p] = sb2p[p]; ff[1][p] = sb2p[p]; }
    {
        const ulonglong2* w12 = reinterpret_cast<const ulonglong2*>(sW1);
        const ulonglong2* w22 = reinterpret_cast<const ulonglong2*>(sW2);
#pragma unroll
        for (int half = 0; half < 2; half++) {
            u64 h[2][8];
#pragma unroll
            for (int p = 0; p < 8; p++) { h[0][p] = sb1p[half*8 + p]; h[1][p] = h[0][p]; }
#pragma unroll
            for (int i = 0; i < 8; i++) {
                u64 d0 = szf[i * ZF_STRIDE + tid];
                u64 d1 = szf[(8 + i) * ZF_STRIDE + tid];
#pragma unroll
                for (int pp = 0; pp < 4; pp++) {
                    ulonglong2 w = w12[i*8 + half*4 + pp];
                    h[0][2*pp]   = fma2(d0, w.x, h[0][2*pp]);
                    h[0][2*pp+1] = fma2(d0, w.y, h[0][2*pp+1]);
                    h[1][2*pp]   = fma2(d1, w.x, h[1][2*pp]);
                    h[1][2*pp+1] = fma2(d1, w.y, h[1][2*pp+1]);
                }
            }
#pragma unroll
            for (int kp8 = 0; kp8 < 8; kp8++) {
                const int kp = half*8 + kp8;
                float h0lo, h0hi, h1lo, h1hi;
                unpack2(h[0][kp8], h0lo, h0hi);
                unpack2(h[1][kp8], h1lo, h1hi);
                u64 e0 = dup2(fmaxf(h0lo, 0.0f)), f0 = dup2(fmaxf(h0hi, 0.0f));
                u64 e1 = dup2(fmaxf(h1lo, 0.0f)), f1 = dup2(fmaxf(h1hi, 0.0f));
                ulonglong2 wa = w22[(2*kp)*2],   wb = w22[(2*kp)*2 + 1];
                ulonglong2 wc = w22[(2*kp+1)*2], wd = w22[(2*kp+1)*2 + 1];
                ff[0][0] = fma2(e0, wa.x, ff[0][0]); ff[0][1] = fma2(e0, wa.y, ff[0][1]);
                ff[0][2] = fma2(e0, wb.x, ff[0][2]); ff[0][3] = fma2(e0, wb.y, ff[0][3]);
                ff[0][0] = fma2(f0, wc.x, ff[0][0]); ff[0][1] = fma2(f0, wc.y, ff[0][1]);
                ff[0][2] = fma2(f0, wd.x, ff[0][2]); ff[0][3] = fma2(f0, wd.y, ff[0][3]);
                ff[1][0] = fma2(e1, wa.x, ff[1][0]); ff[1][1] = fma2(e1, wa.y, ff[1][1]);
                ff[1][2] = fma2(e1, wb.x, ff[1][2]); ff[1][3] = fma2(e1, wb.y, ff[1][3]);
                ff[1][0] = fma2(f1, wc.x, ff[1][0]); ff[1][1] = fma2(f1, wc.y, ff[1][1]);
                ff[1][2] = fma2(f1, wd.x, ff[1][2]); ff[1][3] = fma2(f1, wd.y, ff[1][3]);
            }
        }
    }

    // ---- out = LN(x1 + ffn)*g2 + beta2 (R8 packed form), 16B stores
    ulonglong2* op = reinterpret_cast<ulonglong2*>(out);
#pragma unroll
    for (int T = 0; T < 2; T++) {
        u64 yp[4];
#pragma unroll
        for (int p = 0; p < 4; p++)
            yp[p] = add2(ff[T][p], pack2(x1[T][2*p], x1[T][2*p+1]));
        u64 tA = add2(yp[0], yp[1]);
        u64 tB = add2(yp[2], yp[3]);
        u64 tC = add2(tA, tB);
        float slo, shi; unpack2(tC, slo, shi);
        float m = (slo + shi) * 0.125f;
        u64 negm = dup2(-m);
        u64 dp[4];
#pragma unroll
        for (int p = 0; p < 4; p++) dp[p] = add2(yp[p], negm);
        u64 vr = mul2(dp[0], dp[0]);
        vr = fma2(dp[1], dp[1], vr);
        vr = fma2(dp[2], dp[2], vr);
        vr = fma2(dp[3], dp[3], vr);
        float vlo, vhi; unpack2(vr, vlo, vhi);
        float rs = rsqrtf((vlo + vhi) * 0.125f + 1e-5f);
        u64 rsd = dup2(rs);
        u64 y0 = fma2(mul2(dp[0], rsd), sg2p[0], sbe2p[0]);
        u64 y1 = fma2(mul2(dp[1], rsd), sg2p[1], sbe2p[1]);
        u64 y2 = fma2(mul2(dp[2], rsd), sg2p[2], sbe2p[2]);
        u64 y3 = fma2(mul2(dp[3], rsd), sg2p[3], sbe2p[3]);
        const int t = (T == 0) ? t0 : t1;
        ulonglong2 o0; o0.x = y0; o0.y = y1;
        ulonglong2 o1; o1.x = y2; o1.y = y3;
        op[(size_t)t * 2]     = o0;
        op[(size_t)t * 2 + 1] = o1;
    }
}

extern "C" void kernel_launch(void* const* d_in, const int* in_sizes, int n_in,
                              void* d_out, int out_size)
{
    const float* x          = (const float*)d_in[0];
    const float* Wq         = (const float*)d_in[1];
    const float* bq         = (const float*)d_in[2];
    const float* theta_attn = (const float*)d_in[3];
    const float* Wc         = (const float*)d_in[4];
    const float* bc         = (const float*)d_in[5];
    const float* g1         = (const float*)d_in[6];
    const float* beta1      = (const float*)d_in[7];
    const float* theta_ffn  = (const float*)d_in[8];
    const float* W1         = (const float*)d_in[9];
    const float* b1         = (const float*)d_in[10];
    const float* W2         = (const float*)d_in[11];
    const float* b2         = (const float*)d_in[12];
    const float* g2         = (const float*)d_in[13];
    const float* beta2      = (const float*)d_in[14];
    float* out = (float*)d_out;

    const int blocks = NUM_TOKENS / TOK_PER_BLOCK;   // 2048, exact
    qtb_kernel<<<blocks, THREADS>>>(x, Wq, bq, theta_attn, Wc, bc, g1, beta1,
                                    theta_ffn, W1, b1, W2, b2, g2, beta2, out);
}

// round 13
// speedup vs baseline: 1.9954x; 1.9954x over previous
#include <cuda_runtime.h>

#define THREADS 192
#define TOK_PER_THREAD 3
#define NUM_TOKENS (128 * 8192)
#define TOK_PER_BLOCK (THREADS * TOK_PER_THREAD)   // 576
#define GRID ((NUM_TOKENS + TOK_PER_BLOCK - 1) / TOK_PER_BLOCK)
#define X1_STRIDE 193

typedef unsigned long long u64;

__device__ __forceinline__ u64 pack2(float lo, float hi) {
    u64 r; asm("mov.b64 %0, {%1, %2};" : "=l"(r) : "f"(lo), "f"(hi)); return r;
}
__device__ __forceinline__ u64 dup2(float v) { return pack2(v, v); }
__device__ __forceinline__ void unpack2(u64 p, float& lo, float& hi) {
    asm("mov.b64 {%0, %1}, %2;" : "=f"(lo), "=f"(hi) : "l"(p));
}
__device__ __forceinline__ u64 fma2(u64 a, u64 b, u64 c) {
    u64 d; asm("fma.rn.f32x2 %0, %1, %2, %3;" : "=l"(d) : "l"(a), "l"(b), "l"(c)); return d;
}
__device__ __forceinline__ u64 add2(u64 a, u64 b) {
    u64 d; asm("add.rn.f32x2 %0, %1, %2;" : "=l"(d) : "l"(a), "l"(b)); return d;
}
__device__ __forceinline__ u64 mul2(u64 a, u64 b) {
    u64 d; asm("mul.rn.f32x2 %0, %1, %2;" : "=l"(d) : "l"(a), "l"(b)); return d;
}

__global__ __launch_bounds__(THREADS, 3) void qtb_kernel(
    const float* __restrict__ x,
    const float* __restrict__ Wq,  const float* __restrict__ bq,
    const float* __restrict__ theta_attn,
    const float* __restrict__ Wc,  const float* __restrict__ bc,
    const float* __restrict__ g1,  const float* __restrict__ beta1,
    const float* __restrict__ theta_ffn,
    const float* __restrict__ W1,  const float* __restrict__ b1,
    const float* __restrict__ W2,  const float* __restrict__ b2,
    const float* __restrict__ g2,  const float* __restrict__ beta2,
    float* __restrict__ out)
{
    __shared__ __align__(16) float sWq[64], sWc[64], sW1[256], sW2[256];
    __shared__ __align__(16) u64 sbqth[4], sbcp[4], sb1p[16], sb2p[4];
    __shared__ __align__(16) u64 sg1p[4], sbe1p[4], sg2p[4], sbe2p[4];
    __shared__ float sctf[8];
    __shared__ __align__(16) u64 sx1[12 * X1_STRIDE];   // x1 pairs parked (3 tok x 4 pairs)

    const int tid = threadIdx.x;
    if (tid < 64) { sWq[tid] = Wq[tid]; sWc[tid] = Wc[tid]; }
    for (int i = tid; i < 256; i += THREADS) { sW1[i] = W1[i]; sW2[i] = W2[i]; }
    if (tid < 4) {
        sbqth[tid] = pack2(bq[2*tid] + theta_attn[2*tid], bq[2*tid+1] + theta_attn[2*tid+1]);
        sbcp[tid]  = pack2(bc[2*tid],  bc[2*tid+1]);
        sb2p[tid]  = pack2(b2[2*tid],  b2[2*tid+1]);
        sg1p[tid]  = pack2(g1[2*tid],  g1[2*tid+1]);
        sbe1p[tid] = pack2(beta1[2*tid], beta1[2*tid+1]);
        sg2p[tid]  = pack2(g2[2*tid],  g2[2*tid+1]);
        sbe2p[tid] = pack2(beta2[2*tid], beta2[2*tid+1]);
    }
    if (tid < 16) sb1p[tid] = pack2(b1[2*tid], b1[2*tid+1]);
    if (tid < 8)  sctf[tid] = __cosf(theta_ffn[tid]);
    __syncthreads();

    const int tb = blockIdx.x * TOK_PER_BLOCK + tid;
    int   tok[3];
    bool  vld[3];
#pragma unroll
    for (int T = 0; T < 3; T++) {
        tok[T] = tb + T * THREADS;
        vld[T] = (tok[T] < NUM_TOKENS);
    }
    const float4* xin = reinterpret_cast<const float4*>(x);

    // ---- q = x @ Wq + (bq + theta): x loaded in a scope, consumed, regs die (reload at LN1)
    u64 q[3][4];
#pragma unroll
    for (int T = 0; T < 3; T++)
#pragma unroll
        for (int p = 0; p < 4; p++) q[T][p] = sbqth[p];
    {
        float xs[3][8];
#pragma unroll
        for (int T = 0; T < 3; T++) {
#pragma unroll
            for (int i = 0; i < 8; i++) xs[T][i] = 0.0f;
            if (vld[T]) {
                float4 a0 = xin[(size_t)tok[T] * 2], a1 = xin[(size_t)tok[T] * 2 + 1];
                xs[T][0]=a0.x; xs[T][1]=a0.y; xs[T][2]=a0.z; xs[T][3]=a0.w;
                xs[T][4]=a1.x; xs[T][5]=a1.y; xs[T][6]=a1.z; xs[T][7]=a1.w;
            }
        }
        const ulonglong2* wq2 = reinterpret_cast<const ulonglong2*>(sWq);
#pragma unroll
        for (int j = 0; j < 8; j++) {
            ulonglong2 wa = wq2[j*2], wb = wq2[j*2+1];
            u64 d0 = dup2(xs[0][j]), d1 = dup2(xs[1][j]), d2 = dup2(xs[2][j]);
            q[0][0] = fma2(d0, wa.x, q[0][0]); q[0][1] = fma2(d0, wa.y, q[0][1]);
            q[0][2] = fma2(d0, wb.x, q[0][2]); q[0][3] = fma2(d0, wb.y, q[0][3]);
            q[1][0] = fma2(d1, wa.x, q[1][0]); q[1][1] = fma2(d1, wa.y, q[1][1]);
            q[1][2] = fma2(d1, wb.x, q[1][2]); q[1][3] = fma2(d1, wb.y, q[1][3]);
            q[2][0] = fma2(d2, wa.x, q[2][0]); q[2][1] = fma2(d2, wa.y, q[2][1]);
            q[2][2] = fma2(d2, wb.x, q[2][2]); q[2][3] = fma2(d2, wb.y, q[2][3]);
        }
    }

    // ---- ca = cos(q); z = cumulative products
    float z[3][8];
#pragma unroll
    for (int T = 0; T < 3; T++) {
        float ca[8];
#pragma unroll
        for (int p = 0; p < 4; p++) {
            float lo, hi; unpack2(q[T][p], lo, hi);
            ca[2*p] = __cosf(lo); ca[2*p+1] = __cosf(hi);
        }
        float pref = ca[0];
#pragma unroll
        for (int k = 1; k < 8; k++) { pref *= ca[k]; z[T][k] = pref; }
        float r = ca[1];
#pragma unroll
        for (int k = 2; k < 8; k++) r *= ca[k];
        z[T][0] = r;
    }

    // ---- attn = z @ Wc + bc (reuse q accumulators)
#pragma unroll
    for (int T = 0; T < 3; T++)
#pragma unroll
        for (int p = 0; p < 4; p++) q[T][p] = sbcp[p];
    {
        const ulonglong2* wc2 = reinterpret_cast<const ulonglong2*>(sWc);
#pragma unroll
        for (int j = 0; j < 8; j++) {
            ulonglong2 wa = wc2[j*2], wb = wc2[j*2+1];
            u64 d0 = dup2(z[0][j]), d1 = dup2(z[1][j]), d2 = dup2(z[2][j]);
            q[0][0] = fma2(d0, wa.x, q[0][0]); q[0][1] = fma2(d0, wa.y, q[0][1]);
            q[0][2] = fma2(d0, wb.x, q[0][2]); q[0][3] = fma2(d0, wb.y, q[0][3]);
            q[1][0] = fma2(d1, wa.x, q[1][0]); q[1][1] = fma2(d1, wa.y, q[1][1]);
            q[1][2] = fma2(d1, wb.x, q[1][2]); q[1][3] = fma2(d1, wb.y, q[1][3]);
            q[2][0] = fma2(d2, wa.x, q[2][0]); q[2][1] = fma2(d2, wa.y, q[2][1]);
            q[2][2] = fma2(d2, wb.x, q[2][2]); q[2][3] = fma2(d2, wb.y, q[2][3]);
        }
    }

    // ---- LN1 packed; x reloaded (L1 hit); x1 parked in smem; zf in regs
    float zf[3][8];
#pragma unroll
    for (int T = 0; T < 3; T++) {
        u64 vp[4];
        if (vld[T]) {
            float4 a0 = xin[(size_t)tok[T] * 2], a1 = xin[(size_t)tok[T] * 2 + 1];
            vp[0] = add2(q[T][0], pack2(a0.x, a0.y));
            vp[1] = add2(q[T][1], pack2(a0.z, a0.w));
            vp[2] = add2(q[T][2], pack2(a1.x, a1.y));
            vp[3] = add2(q[T][3], pack2(a1.z, a1.w));
        } else {
#pragma unroll
            for (int p = 0; p < 4; p++) vp[p] = q[T][p];
        }
        u64 tA = add2(vp[0], vp[1]);
        u64 tB = add2(vp[2], vp[3]);
        u64 tC = add2(tA, tB);
        float slo, shi; unpack2(tC, slo, shi);
        float m = (slo + shi) * 0.125f;
        u64 negm = dup2(-m);
        u64 dp[4];
#pragma unroll
        for (int p = 0; p < 4; p++) dp[p] = add2(vp[p], negm);
        u64 vr = mul2(dp[0], dp[0]);
        vr = fma2(dp[1], dp[1], vr);
        vr = fma2(dp[2], dp[2], vr);
        vr = fma2(dp[3], dp[3], vr);
        float vlo, vhi; unpack2(vr, vlo, vhi);
        float rs = rsqrtf((vlo + vhi) * 0.125f + 1e-5f);
        u64 rsd = dup2(rs);
#pragma unroll
        for (int p = 0; p < 4; p++) {
            u64 x1p = fma2(mul2(dp[p], rsd), sg1p[p], sbe1p[p]);
            sx1[(T*4 + p) * X1_STRIDE + tid] = x1p;
            float lo, hi; unpack2(x1p, lo, hi);
            zf[T][2*p]   = sctf[2*p]   * __cosf(lo);
            zf[T][2*p+1] = sctf[2*p+1] * __cosf(hi);
        }
    }

    // ---- FFN, two k-halves (R10-proven): h[3][8] packed chains, dups hoisted per-i.
    u64 ff[3][4];
#pragma unroll
    for (int T = 0; T < 3; T++)
#pragma unroll
        for (int p = 0; p < 4; p++) ff[T][p] = sb2p[p];
    {
        const ulonglong2* w12 = reinterpret_cast<const ulonglong2*>(sW1);
        const ulonglong2* w22 = reinterpret_cast<const ulonglong2*>(sW2);
#pragma unroll
        for (int half = 0; half < 2; half++) {
            u64 h[3][8];
#pragma unroll
            for (int p = 0; p < 8; p++) {
                h[0][p] = sb1p[half*8 + p]; h[1][p] = h[0][p]; h[2][p] = h[0][p];
            }
#pragma unroll
            for (int i = 0; i < 8; i++) {
                u64 d0 = dup2(zf[0][i]), d1 = dup2(zf[1][i]), d2 = dup2(zf[2][i]);
#pragma unroll
                for (int pp = 0; pp < 4; pp++) {
                    ulonglong2 w = w12[i*8 + half*4 + pp];
                    h[0][2*pp]   = fma2(d0, w.x, h[0][2*pp]);
                    h[0][2*pp+1] = fma2(d0, w.y, h[0][2*pp+1]);
                    h[1][2*pp]   = fma2(d1, w.x, h[1][2*pp]);
                    h[1][2*pp+1] = fma2(d1, w.y, h[1][2*pp+1]);
                    h[2][2*pp]   = fma2(d2, w.x, h[2][2*pp]);
                    h[2][2*pp+1] = fma2(d2, w.y, h[2][2*pp+1]);
                }
            }
#pragma unroll
            for (int kp8 = 0; kp8 < 8; kp8++) {
                const int kp = half*8 + kp8;
                float h0lo, h0hi, h1lo, h1hi, h2lo, h2hi;
                unpack2(h[0][kp8], h0lo, h0hi);
                unpack2(h[1][kp8], h1lo, h1hi);
                unpack2(h[2][kp8], h2lo, h2hi);
                u64 e0 = dup2(fmaxf(h0lo, 0.0f)), f0 = dup2(fmaxf(h0hi, 0.0f));
                u64 e1 = dup2(fmaxf(h1lo, 0.0f)), f1 = dup2(fmaxf(h1hi, 0.0f));
                u64 e2 = dup2(fmaxf(h2lo, 0.0f)), f2 = dup2(fmaxf(h2hi, 0.0f));
                ulonglong2 wa = w22[(2*kp)*2],   wb = w22[(2*kp)*2 + 1];
                ulonglong2 wc = w22[(2*kp+1)*2], wd = w22[(2*kp+1)*2 + 1];
                ff[0][0] = fma2(e0, wa.x, ff[0][0]); ff[0][1] = fma2(e0, wa.y, ff[0][1]);
                ff[0][2] = fma2(e0, wb.x, ff[0][2]); ff[0][3] = fma2(e0, wb.y, ff[0][3]);
                ff[0][0] = fma2(f0, wc.x, ff[0][0]); ff[0][1] = fma2(f0, wc.y, ff[0][1]);
                ff[0][2] = fma2(f0, wd.x, ff[0][2]); ff[0][3] = fma2(f0, wd.y, ff[0][3]);
                ff[1][0] = fma2(e1, wa.x, ff[1][0]); ff[1][1] = fma2(e1, wa.y, ff[1][1]);
                ff[1][2] = fma2(e1, wb.x, ff[1][2]); ff[1][3] = fma2(e1, wb.y, ff[1][3]);
                ff[1][0] = fma2(f1, wc.x, ff[1][0]); ff[1][1] = fma2(f1, wc.y, ff[1][1]);
                ff[1][2] = fma2(f1, wd.x, ff[1][2]); ff[1][3] = fma2(f1, wd.y, ff[1][3]);
                ff[2][0] = fma2(e2, wa.x, ff[2][0]); ff[2][1] = fma2(e2, wa.y, ff[2][1]);
                ff[2][2] = fma2(e2, wb.x, ff[2][2]); ff[2][3] = fma2(e2, wb.y, ff[2][3]);
                ff[2][0] = fma2(f2, wc.x, ff[2][0]); ff[2][1] = fma2(f2, wc.y, ff[2][1]);
                ff[2][2] = fma2(f2, wd.x, ff[2][2]); ff[2][3] = fma2(f2, wd.y, ff[2][3]);
            }
        }
    }

    // ---- out = LN(x1 + ffn)*g2 + beta2, packed, 16B stores
    ulonglong2* op = reinterpret_cast<ulonglong2*>(out);
#pragma unroll
    for (int T = 0; T < 3; T++) {
        u64 yp[4];
#pragma unroll
        for (int p = 0; p < 4; p++)
            yp[p] = add2(ff[T][p], sx1[(T*4 + p) * X1_STRIDE + tid]);
        u64 tA = add2(yp[0], yp[1]);
        u64 tB = add2(yp[2], yp[3]);
        u64 tC = add2(tA, tB);
        float slo, shi; unpack2(tC, slo, shi);
        float m = (slo + shi) * 0.125f;
        u64 negm = dup2(-m);
        u64 dp[4];
#pragma unroll
        for (int p = 0; p < 4; p++) dp[p] = add2(yp[p], negm);
        u64 vr = mul2(dp[0], dp[0]);
        vr = fma2(dp[1], dp[1], vr);
        vr = fma2(dp[2], dp[2], vr);
        vr = fma2(dp[3], dp[3], vr);
        float vlo, vhi; unpack2(vr, vlo, vhi);
        float rs = rsqrtf((vlo + vhi) * 0.125f + 1e-5f);
        u64 rsd = dup2(rs);
        u64 y0 = fma2(mul2(dp[0], rsd), sg2p[0], sbe2p[0]);
        u64 y1 = fma2(mul2(dp[1], rsd), sg2p[1], sbe2p[1]);
        u64 y2 = fma2(mul2(dp[2], rsd), sg2p[2], sbe2p[2]);
        u64 y3 = fma2(mul2(dp[3], rsd), sg2p[3], sbe2p[3]);
        if (vld[T]) {
            ulonglong2 o0; o0.x = y0; o0.y = y1;
            ulonglong2 o1; o1.x = y2; o1.y = y3;
            op[(size_t)tok[T] * 2]     = o0;
            op[(size_t)tok[T] * 2 + 1] = o1;
        }
    }
}

extern "C" void kernel_launch(void* const* d_in, const int* in_sizes, int n_in,
                              void* d_out, int out_size)
{
    const float* x          = (const float*)d_in[0];
    const float* Wq         = (const float*)d_in[1];
    const float* bq         = (const float*)d_in[2];
    const float* theta_attn = (const float*)d_in[3];
    const float* Wc         = (const float*)d_in[4];
    const float* bc         = (const float*)d_in[5];
    const float* g1         = (const float*)d_in[6];
    const float* beta1      = (const float*)d_in[7];
    const float* theta_ffn  = (const float*)d_in[8];
    const float* W1         = (const float*)d_in[9];
    const float* b1         = (const float*)d_in[10];
    const float* W2         = (const float*)d_in[11];
    const float* b2         = (const float*)d_in[12];
    const float* g2         = (const float*)d_in[13];
    const float* beta2      = (const float*)d_in[14];
    float* out = (float*)d_out;

    qtb_kernel<<<GRID, THREADS>>>(x, Wq, bq, theta_attn, Wc, bc, g1, beta1,
                                  theta_ffn, W1, b1, W2, b2, g2, beta2, out);
}

// round 14
// speedup vs baseline: 2.2392x; 1.1222x over previous
#include <cuda_runtime.h>

#define THREADS 256
#define TOK_PER_THREAD 3
#define NUM_TOKENS (128 * 8192)
#define TOK_PER_BLOCK (THREADS * TOK_PER_THREAD)   // 768
#define GRID ((NUM_TOKENS + TOK_PER_BLOCK - 1) / TOK_PER_BLOCK)
#define X1_STRIDE 257

typedef unsigned long long u64;

__device__ __forceinline__ u64 pack2(float lo, float hi) {
    u64 r; asm("mov.b64 %0, {%1, %2};" : "=l"(r) : "f"(lo), "f"(hi)); return r;
}
__device__ __forceinline__ u64 dup2(float v) { return pack2(v, v); }
__device__ __forceinline__ void unpack2(u64 p, float& lo, float& hi) {
    asm("mov.b64 {%0, %1}, %2;" : "=f"(lo), "=f"(hi) : "l"(p));
}
__device__ __forceinline__ u64 fma2(u64 a, u64 b, u64 c) {
    u64 d; asm("fma.rn.f32x2 %0, %1, %2, %3;" : "=l"(d) : "l"(a), "l"(b), "l"(c)); return d;
}
__device__ __forceinline__ u64 add2(u64 a, u64 b) {
    u64 d; asm("add.rn.f32x2 %0, %1, %2;" : "=l"(d) : "l"(a), "l"(b)); return d;
}
__device__ __forceinline__ u64 mul2(u64 a, u64 b) {
    u64 d; asm("mul.rn.f32x2 %0, %1, %2;" : "=l"(d) : "l"(a), "l"(b)); return d;
}

__global__ __launch_bounds__(THREADS, 2) void qtb_kernel(
    const float* __restrict__ x,
    const float* __restrict__ Wq,  const float* __restrict__ bq,
    const float* __restrict__ theta_attn,
    const float* __restrict__ Wc,  const float* __restrict__ bc,
    const float* __restrict__ g1,  const float* __restrict__ beta1,
    const float* __restrict__ theta_ffn,
    const float* __restrict__ W1,  const float* __restrict__ b1,
    const float* __restrict__ W2,  const float* __restrict__ b2,
    const float* __restrict__ g2,  const float* __restrict__ beta2,
    float* __restrict__ out)
{
    __shared__ __align__(16) float sWq[64], sWc[64], sW1[256], sW2[256];
    __shared__ __align__(16) u64 sbqth[4], sbcp[4], sb1p[16], sb2p[4];
    __shared__ __align__(16) u64 sg1p[4], sbe1p[4], sg2p[4], sbe2p[4];
    __shared__ __align__(16) u64 sx1[12 * X1_STRIDE];   // x1 pairs parked (3 tok x 4 pairs)

    const int tid = threadIdx.x;
    if (tid < 64) { sWq[tid] = Wq[tid]; sWc[tid] = Wc[tid]; }
    // ctf folded into W1: h_k = sum_i cos(x1_i) * (ctf_i * W1[i][k]) + b1_k
    sW1[tid] = __cosf(theta_ffn[tid >> 5]) * W1[tid];
    sW2[tid] = W2[tid];
    if (tid < 4) {
        sbqth[tid] = pack2(bq[2*tid] + theta_attn[2*tid], bq[2*tid+1] + theta_attn[2*tid+1]);
        sbcp[tid]  = pack2(bc[2*tid],  bc[2*tid+1]);
        sb2p[tid]  = pack2(b2[2*tid],  b2[2*tid+1]);
        sg1p[tid]  = pack2(g1[2*tid],  g1[2*tid+1]);
        sbe1p[tid] = pack2(beta1[2*tid], beta1[2*tid+1]);
        sg2p[tid]  = pack2(g2[2*tid],  g2[2*tid+1]);
        sbe2p[tid] = pack2(beta2[2*tid], beta2[2*tid+1]);
    }
    if (tid < 16) sb1p[tid] = pack2(b1[2*tid], b1[2*tid+1]);
    __syncthreads();

    const int tb = blockIdx.x * TOK_PER_BLOCK + tid;
    int   tok[3];
    bool  vld[3];
#pragma unroll
    for (int T = 0; T < 3; T++) {
        tok[T] = tb + T * THREADS;
        vld[T] = (tok[T] < NUM_TOKENS);
    }

    // per-thread x1 slot: compile-time row offsets from this base
    u64* const px1 = sx1 + tid;

    // ---- load tokens (guarded for tail)
    float xs[3][8];
#pragma unroll
    for (int T = 0; T < 3; T++) {
#pragma unroll
        for (int i = 0; i < 8; i++) xs[T][i] = 0.0f;
        if (vld[T]) {
            const float4* xin = reinterpret_cast<const float4*>(x) + (size_t)tok[T] * 2;
            float4 a0 = xin[0], a1 = xin[1];
            xs[T][0]=a0.x; xs[T][1]=a0.y; xs[T][2]=a0.z; xs[T][3]=a0.w;
            xs[T][4]=a1.x; xs[T][5]=a1.y; xs[T][6]=a1.z; xs[T][7]=a1.w;
        }
    }

    // ---- q = x @ Wq + (bq + theta): packed outputs, 3 tokens share weight loads
    u64 q[3][4];
#pragma unroll
    for (int T = 0; T < 3; T++)
#pragma unroll
        for (int p = 0; p < 4; p++) q[T][p] = sbqth[p];
    {
        const ulonglong2* wq2 = reinterpret_cast<const ulonglong2*>(sWq);
#pragma unroll
        for (int j = 0; j < 8; j++) {
            ulonglong2 wa = wq2[j*2], wb = wq2[j*2+1];
            u64 d0 = dup2(xs[0][j]), d1 = dup2(xs[1][j]), d2 = dup2(xs[2][j]);
            q[0][0] = fma2(d0, wa.x, q[0][0]); q[0][1] = fma2(d0, wa.y, q[0][1]);
            q[0][2] = fma2(d0, wb.x, q[0][2]); q[0][3] = fma2(d0, wb.y, q[0][3]);
            q[1][0] = fma2(d1, wa.x, q[1][0]); q[1][1] = fma2(d1, wa.y, q[1][1]);
            q[1][2] = fma2(d1, wb.x, q[1][2]); q[1][3] = fma2(d1, wb.y, q[1][3]);
            q[2][0] = fma2(d2, wa.x, q[2][0]); q[2][1] = fma2(d2, wa.y, q[2][1]);
            q[2][2] = fma2(d2, wb.x, q[2][2]); q[2][3] = fma2(d2, wb.y, q[2][3]);
        }
    }

    // ---- ca = cos(q); z = cumulative products
    float z[3][8];
#pragma unroll
    for (int T = 0; T < 3; T++) {
        float ca[8];
#pragma unroll
        for (int p = 0; p < 4; p++) {
            float lo, hi; unpack2(q[T][p], lo, hi);
            ca[2*p] = __cosf(lo); ca[2*p+1] = __cosf(hi);
        }
        float pref = ca[0];
#pragma unroll
        for (int k = 1; k < 8; k++) { pref *= ca[k]; z[T][k] = pref; }
        float r = ca[1];
#pragma unroll
        for (int k = 2; k < 8; k++) r *= ca[k];
        z[T][0] = r;
    }

    // ---- attn = z @ Wc + bc (reuse q accumulators)
#pragma unroll
    for (int T = 0; T < 3; T++)
#pragma unroll
        for (int p = 0; p < 4; p++) q[T][p] = sbcp[p];
    {
        const ulonglong2* wc2 = reinterpret_cast<const ulonglong2*>(sWc);
#pragma unroll
        for (int j = 0; j < 8; j++) {
            ulonglong2 wa = wc2[j*2], wb = wc2[j*2+1];
            u64 d0 = dup2(z[0][j]), d1 = dup2(z[1][j]), d2 = dup2(z[2][j]);
            q[0][0] = fma2(d0, wa.x, q[0][0]); q[0][1] = fma2(d0, wa.y, q[0][1]);
            q[0][2] = fma2(d0, wb.x, q[0][2]); q[0][3] = fma2(d0, wb.y, q[0][3]);
            q[1][0] = fma2(d1, wa.x, q[1][0]); q[1][1] = fma2(d1, wa.y, q[1][1]);
            q[1][2] = fma2(d1, wb.x, q[1][2]); q[1][3] = fma2(d1, wb.y, q[1][3]);
            q[2][0] = fma2(d2, wa.x, q[2][0]); q[2][1] = fma2(d2, wa.y, q[2][1]);
            q[2][2] = fma2(d2, wb.x, q[2][2]); q[2][3] = fma2(d2, wb.y, q[2][3]);
        }
    }

    // ---- LN1 packed; x1 pairs parked in smem (constant offsets); zf = cos(x1) (ctf folded)
    float zf[3][8];
#pragma unroll
    for (int T = 0; T < 3; T++) {
        u64 vp[4];
#pragma unroll
        for (int p = 0; p < 4; p++)
            vp[p] = add2(q[T][p], pack2(xs[T][2*p], xs[T][2*p+1]));
        u64 tA = add2(vp[0], vp[1]);
        u64 tB = add2(vp[2], vp[3]);
        u64 tC = add2(tA, tB);
        float slo, shi; unpack2(tC, slo, shi);
        float m = (slo + shi) * 0.125f;
        u64 negm = dup2(-m);
        u64 dp[4];
#pragma unroll
        for (int p = 0; p < 4; p++) dp[p] = add2(vp[p], negm);
        u64 vr = mul2(dp[0], dp[0]);
        vr = fma2(dp[1], dp[1], vr);
        vr = fma2(dp[2], dp[2], vr);
        vr = fma2(dp[3], dp[3], vr);
        float vlo, vhi; unpack2(vr, vlo, vhi);
        float rs = rsqrtf((vlo + vhi) * 0.125f + 1e-5f);
        u64 rsd = dup2(rs);
#pragma unroll
        for (int p = 0; p < 4; p++) {
            u64 x1p = fma2(mul2(dp[p], rsd), sg1p[p], sbe1p[p]);
            px1[(T*4 + p) * X1_STRIDE] = x1p;
            float lo, hi; unpack2(x1p, lo, hi);
            zf[T][2*p]   = __cosf(lo);
            zf[T][2*p+1] = __cosf(hi);
        }
    }

    // ---- FFN, two k-halves (R10-proven): h[3][8] packed chains, dups hoisted per-i.
    u64 ff[3][4];
#pragma unroll
    for (int T = 0; T < 3; T++)
#pragma unroll
        for (int p = 0; p < 4; p++) ff[T][p] = sb2p[p];
    {
        const ulonglong2* w12 = reinterpret_cast<const ulonglong2*>(sW1);
        const ulonglong2* w22 = reinterpret_cast<const ulonglong2*>(sW2);
#pragma unroll
        for (int half = 0; half < 2; half++) {
            u64 h[3][8];
#pragma unroll
            for (int p = 0; p < 8; p++) {
                h[0][p] = sb1p[half*8 + p]; h[1][p] = h[0][p]; h[2][p] = h[0][p];
            }
#pragma unroll
            for (int i = 0; i < 8; i++) {
                u64 d0 = dup2(zf[0][i]), d1 = dup2(zf[1][i]), d2 = dup2(zf[2][i]);
#pragma unroll
                for (int pp = 0; pp < 4; pp++) {
                    ulonglong2 w = w12[i*8 + half*4 + pp];
                    h[0][2*pp]   = fma2(d0, w.x, h[0][2*pp]);
                    h[0][2*pp+1] = fma2(d0, w.y, h[0][2*pp+1]);
                    h[1][2*pp]   = fma2(d1, w.x, h[1][2*pp]);
                    h[1][2*pp+1] = fma2(d1, w.y, h[1][2*pp+1]);
                    h[2][2*pp]   = fma2(d2, w.x, h[2][2*pp]);
                    h[2][2*pp+1] = fma2(d2, w.y, h[2][2*pp+1]);
                }
            }
#pragma unroll
            for (int kp8 = 0; kp8 < 8; kp8++) {
                const int kp = half*8 + kp8;
                float h0lo, h0hi, h1lo, h1hi, h2lo, h2hi;
                unpack2(h[0][kp8], h0lo, h0hi);
                unpack2(h[1][kp8], h1lo, h1hi);
                unpack2(h[2][kp8], h2lo, h2hi);
                u64 e0 = dup2(fmaxf(h0lo, 0.0f)), f0 = dup2(fmaxf(h0hi, 0.0f));
                u64 e1 = dup2(fmaxf(h1lo, 0.0f)), f1 = dup2(fmaxf(h1hi, 0.0f));
                u64 e2 = dup2(fmaxf(h2lo, 0.0f)), f2 = dup2(fmaxf(h2hi, 0.0f));
                ulonglong2 wa = w22[(2*kp)*2],   wb = w22[(2*kp)*2 + 1];
                ulonglong2 wc = w22[(2*kp+1)*2], wd = w22[(2*kp+1)*2 + 1];
                ff[0][0] = fma2(e0, wa.x, ff[0][0]); ff[0][1] = fma2(e0, wa.y, ff[0][1]);
                ff[0][2] = fma2(e0, wb.x, ff[0][2]); ff[0][3] = fma2(e0, wb.y, ff[0][3]);
                ff[0][0] = fma2(f0, wc.x, ff[0][0]); ff[0][1] = fma2(f0, wc.y, ff[0][1]);
                ff[0][2] = fma2(f0, wd.x, ff[0][2]); ff[0][3] = fma2(f0, wd.y, ff[0][3]);
                ff[1][0] = fma2(e1, wa.x, ff[1][0]); ff[1][1] = fma2(e1, wa.y, ff[1][1]);
                ff[1][2] = fma2(e1, wb.x, ff[1][2]); ff[1][3] = fma2(e1, wb.y, ff[1][3]);
                ff[1][0] = fma2(f1, wc.x, ff[1][0]); ff[1][1] = fma2(f1, wc.y, ff[1][1]);
                ff[1][2] = fma2(f1, wd.x, ff[1][2]); ff[1][3] = fma2(f1, wd.y, ff[1][3]);
                ff[2][0] = fma2(e2, wa.x, ff[2][0]); ff[2][1] = fma2(e2, wa.y, ff[2][1]);
                ff[2][2] = fma2(e2, wb.x, ff[2][2]); ff[2][3] = fma2(e2, wb.y, ff[2][3]);
                ff[2][0] = fma2(f2, wc.x, ff[2][0]); ff[2][1] = fma2(f2, wc.y, ff[2][1]);
                ff[2][2] = fma2(f2, wd.x, ff[2][2]); ff[2][3] = fma2(f2, wd.y, ff[2][3]);
            }
        }
    }

    // ---- out = LN(x1 + ffn)*g2 + beta2, packed, 16B stores
    ulonglong2* op = reinterpret_cast<ulonglong2*>(out);
#pragma unroll
    for (int T = 0; T < 3; T++) {
        u64 yp[4];
#pragma unroll
        for (int p = 0; p < 4; p++)
            yp[p] = add2(ff[T][p], px1[(T*4 + p) * X1_STRIDE]);
        u64 tA = add2(yp[0], yp[1]);
        u64 tB = add2(yp[2], yp[3]);
        u64 tC = add2(tA, tB);
        float slo, shi; unpack2(tC, slo, shi);
        float m = (slo + shi) * 0.125f;
        u64 negm = dup2(-m);
        u64 dp[4];
#pragma unroll
        for (int p = 0; p < 4; p++) dp[p] = add2(yp[p], negm);
        u64 vr = mul2(dp[0], dp[0]);
        vr = fma2(dp[1], dp[1], vr);
        vr = fma2(dp[2], dp[2], vr);
        vr = fma2(dp[3], dp[3], vr);
        float vlo, vhi; unpack2(vr, vlo, vhi);
        float rs = rsqrtf((vlo + vhi) * 0.125f + 1e-5f);
        u64 rsd = dup2(rs);
        u64 y0 = fma2(mul2(dp[0], rsd), sg2p[0], sbe2p[0]);
        u64 y1 = fma2(mul2(dp[1], rsd), sg2p[1], sbe2p[1]);
        u64 y2 = fma2(mul2(dp[2], rsd), sg2p[2], sbe2p[2]);
        u64 y3 = fma2(mul2(dp[3], rsd), sg2p[3], sbe2p[3]);
        if (vld[T]) {
            ulonglong2 o0; o0.x = y0; o0.y = y1;
            ulonglong2 o1; o1.x = y2; o1.y = y3;
            op[(size_t)tok[T] * 2]     = o0;
            op[(size_t)tok[T] * 2 + 1] = o1;
        }
    }
}

extern "C" void kernel_launch(void* const* d_in, const int* in_sizes, int n_in,
                              void* d_out, int out_size)
{
    const float* x          = (const float*)d_in[0];
    const float* Wq         = (const float*)d_in[1];
    const float* bq         = (const float*)d_in[2];
    const float* theta_attn = (const float*)d_in[3];
    const float* Wc         = (const float*)d_in[4];
    const float* bc         = (const float*)d_in[5];
    const float* g1         = (const float*)d_in[6];
    const float* beta1      = (const float*)d_in[7];
    const float* theta_ffn  = (const float*)d_in[8];
    const float* W1         = (const float*)d_in[9];
    const float* b1         = (const float*)d_in[10];
    const float* W2         = (const float*)d_in[11];
    const float* b2         = (const float*)d_in[12];
    const float* g2         = (const float*)d_in[13];
    const float* beta2      = (const float*)d_in[14];
    float* out = (float*)d_out;

    qtb_kernel<<<GRID, THREADS>>>(x, Wq, bq, theta_attn, Wc, bc, g1, beta1,
                                  theta_ffn, W1, b1, W2, b2, g2, beta2, out);
}